// round 2
// baseline (speedup 1.0000x reference)
#include <cuda_runtime.h>
#include <cstdint>
#include <cstdio>

#define B_   1024
#define V_   50257
#define E_   128
#define NBK  393          // ceil(V/128)

#define AS_STRIDE 132     // 128 + 4 pad -> conflict-free A frag loads
#define BS_STRIDE 36      // 32 + 4 pad  -> conflict-free B frag loads
#define SMEM_FLOATS (128*AS_STRIDE + 128*BS_STRIDE)
#define SMEM_BYTES  (SMEM_FLOATS*4)

// ---------------- device scratch (no allocation allowed) ----------------
__device__ int   g_idx[B_];
__device__ float g_q[B_*E_];
__device__ float g_pmax[B_*NBK];
__device__ float g_psum[B_*NBK];
__device__ float g_lse[B_];

// ---------------- helpers ----------------
__device__ __forceinline__ unsigned f2tf32(float x){
    unsigned u; asm("cvt.rna.tf32.f32 %0, %1;" : "=r"(u) : "f"(x)); return u;
}

__device__ __forceinline__ void lse_merge(float& m, float& s, float m2, float s2){
    float M = fmaxf(m, m2);
    s = s*__expf(m - M) + s2*__expf(m2 - M);
    m = M;
}

__device__ __forceinline__ void mma_tf32(float c[4], unsigned a0, unsigned a1,
                                         unsigned a2, unsigned a3,
                                         unsigned b0, unsigned b1){
    asm volatile(
        "mma.sync.aligned.m16n8k8.row.col.f32.tf32.tf32.f32 "
        "{%0,%1,%2,%3}, {%4,%5,%6,%7}, {%8,%9}, {%0,%1,%2,%3};\n"
        : "+f"(c[0]), "+f"(c[1]), "+f"(c[2]), "+f"(c[3])
        : "r"(a0), "r"(a1), "r"(a2), "r"(a3), "r"(b0), "r"(b1));
}

// ---------------- kernel 1: one-hot index extraction ----------------
__global__ void k_findidx(const float4* __restrict__ xs){
    long n4 = (long)B_*V_/4;
    for (long i = (long)blockIdx.x*blockDim.x + threadIdx.x; i < n4;
         i += (long)gridDim.x*blockDim.x){
        float4 v = xs[i];
        if (v.x!=0.f || v.y!=0.f || v.z!=0.f || v.w!=0.f){
            long base = i*4;
            if (v.x!=0.f){ long f=base;   g_idx[f/V_] = (int)(f%V_); }
            if (v.y!=0.f){ long f=base+1; g_idx[f/V_] = (int)(f%V_); }
            if (v.z!=0.f){ long f=base+2; g_idx[f/V_] = (int)(f%V_); }
            if (v.w!=0.f){ long f=base+3; g_idx[f/V_] = (int)(f%V_); }
        }
    }
}

// ---------------- kernel 2: q[b] = EMBEDM[idx[b]] @ metric ----------------
__global__ void k_q(const float* __restrict__ emb, const float* __restrict__ metric){
    __shared__ float se[E_];
    int b = blockIdx.x, t = threadIdx.x;
    int id = g_idx[b];
    se[t] = emb[(size_t)id*E_ + t];
    __syncthreads();
    float acc = 0.f;
    #pragma unroll 16
    for (int k = 0; k < E_; k++) acc = fmaf(se[k], metric[k*E_ + t], acc);
    g_q[b*E_ + t] = acc;
}

// ---------------- kernel 3/5: tf32 GEMM, templated epilogue ----------------
// EPI=0 : online per-row (max, sumexp) -> partials
// EPI=1 : out[r][v] = score - lse[r]
template<int EPI>
__global__ __launch_bounds__(256, 2) void k_gemm(const float* __restrict__ neg,
                                                 float* __restrict__ out){
    extern __shared__ float sm[];
    float* As = sm;                    // [128][AS_STRIDE]
    float* Bs = sm + 128*AS_STRIDE;    // [128][BS_STRIDE]

    const int t    = threadIdx.x;
    const int lane = t & 31, wid = t >> 5;
    const int wm   = wid & 3;          // 4 warps in M -> 32 rows each
    const int wn   = wid >> 2;         // 2 warps in N -> 64 cols each
    const int g    = lane >> 2, tid4 = lane & 3;
    const int nb = blockIdx.x, mb = blockIdx.y;
    const int v0 = nb*128, m0 = mb*128;

    // ---- load full-K A tile (q), convert to tf32 ----
    {
        const float4* q4 = (const float4*)(g_q + (size_t)m0*E_);
        #pragma unroll
        for (int j = 0; j < 16; j++){
            int f = t + 256*j;
            int row = f >> 5, c4 = f & 31;
            float4 v = q4[row*32 + c4];
            v.x = __uint_as_float(f2tf32(v.x));
            v.y = __uint_as_float(f2tf32(v.y));
            v.z = __uint_as_float(f2tf32(v.z));
            v.w = __uint_as_float(f2tf32(v.w));
            *(float4*)(As + row*AS_STRIDE + c4*4) = v;
        }
    }

    float acc[2][8][4];
    #pragma unroll
    for (int mi = 0; mi < 2; mi++)
        #pragma unroll
        for (int ni = 0; ni < 8; ni++)
            #pragma unroll
            for (int c = 0; c < 4; c++) acc[mi][ni][c] = 0.f;

    // ---- main loop over K chunks of 32 ----
    for (int kc = 0; kc < E_; kc += 32){
        #pragma unroll
        for (int j = 0; j < 4; j++){
            int f = t + 256*j;
            int n = f >> 3, k4 = f & 7;
            float4 v = make_float4(0.f,0.f,0.f,0.f);
            int vrow = v0 + n;
            if (vrow < V_) v = *(const float4*)(neg + (size_t)vrow*E_ + kc + k4*4);
            v.x = __uint_as_float(f2tf32(v.x));
            v.y = __uint_as_float(f2tf32(v.y));
            v.z = __uint_as_float(f2tf32(v.z));
            v.w = __uint_as_float(f2tf32(v.w));
            *(float4*)(Bs + n*BS_STRIDE + k4*4) = v;
        }
        __syncthreads();

        #pragma unroll
        for (int k8 = 0; k8 < 4; k8++){
            const int kA = kc + k8*8;       // col into As
            const int kB = k8*8;            // col into Bs (chunk-local)
            unsigned b0r[8], b1r[8];
            #pragma unroll
            for (int ni = 0; ni < 8; ni++){
                int n = wn*64 + ni*8 + g;
                b0r[ni] = __float_as_uint(Bs[n*BS_STRIDE + kB + tid4]);
                b1r[ni] = __float_as_uint(Bs[n*BS_STRIDE + kB + tid4 + 4]);
            }
            #pragma unroll
            for (int mi = 0; mi < 2; mi++){
                int m = wm*32 + mi*16;
                unsigned a0 = __float_as_uint(As[(m+g  )*AS_STRIDE + kA + tid4]);
                unsigned a1 = __float_as_uint(As[(m+8+g)*AS_STRIDE + kA + tid4]);
                unsigned a2 = __float_as_uint(As[(m+g  )*AS_STRIDE + kA + tid4 + 4]);
                unsigned a3 = __float_as_uint(As[(m+8+g)*AS_STRIDE + kA + tid4 + 4]);
                #pragma unroll
                for (int ni = 0; ni < 8; ni++)
                    mma_tf32(acc[mi][ni], a0, a1, a2, a3, b0r[ni], b1r[ni]);
            }
        }
        __syncthreads();
    }

    if (EPI == 0){
        // per-thread rows: (mi, half) -> row m0 + wm*32 + mi*16 + half*8 + g
        float rm[2][2] = {{-1e30f,-1e30f},{-1e30f,-1e30f}};
        float rs[2][2] = {{0.f,0.f},{0.f,0.f}};
        #pragma unroll
        for (int mi = 0; mi < 2; mi++)
            #pragma unroll
            for (int ni = 0; ni < 8; ni++){
                int col0 = v0 + wn*64 + ni*8 + 2*tid4;
                if (col0   < V_){ rm[mi][0] = fmaxf(rm[mi][0], acc[mi][ni][0]);
                                  rm[mi][1] = fmaxf(rm[mi][1], acc[mi][ni][2]); }
                if (col0+1 < V_){ rm[mi][0] = fmaxf(rm[mi][0], acc[mi][ni][1]);
                                  rm[mi][1] = fmaxf(rm[mi][1], acc[mi][ni][3]); }
            }
        #pragma unroll
        for (int mi = 0; mi < 2; mi++)
            #pragma unroll
            for (int ni = 0; ni < 8; ni++){
                int col0 = v0 + wn*64 + ni*8 + 2*tid4;
                if (col0   < V_){ rs[mi][0] += __expf(acc[mi][ni][0] - rm[mi][0]);
                                  rs[mi][1] += __expf(acc[mi][ni][2] - rm[mi][1]); }
                if (col0+1 < V_){ rs[mi][0] += __expf(acc[mi][ni][1] - rm[mi][0]);
                                  rs[mi][1] += __expf(acc[mi][ni][3] - rm[mi][1]); }
            }
        // reduce across the 4 lanes sharing each row (tid4)
        #pragma unroll
        for (int mi = 0; mi < 2; mi++)
            #pragma unroll
            for (int h = 0; h < 2; h++)
                #pragma unroll
                for (int off = 1; off <= 2; off <<= 1){
                    float m2 = __shfl_xor_sync(0xffffffffu, rm[mi][h], off);
                    float s2 = __shfl_xor_sync(0xffffffffu, rs[mi][h], off);
                    lse_merge(rm[mi][h], rs[mi][h], m2, s2);
                }
        // cross-warp (wn) merge via smem (reuse As region; prior sync done)
        float* red = sm;   // [128 rows][2 wn][2]
        if (tid4 == 0){
            #pragma unroll
            for (int mi = 0; mi < 2; mi++)
                #pragma unroll
                for (int h = 0; h < 2; h++){
                    int rl = wm*32 + mi*16 + h*8 + g;
                    red[rl*4 + wn*2 + 0] = rm[mi][h];
                    red[rl*4 + wn*2 + 1] = rs[mi][h];
                }
        }
        __syncthreads();
        if (t < 128){
            float m = red[t*4 + 0], s = red[t*4 + 1];
            lse_merge(m, s, red[t*4 + 2], red[t*4 + 3]);
            g_pmax[(size_t)(m0 + t)*NBK + nb] = m;
            g_psum[(size_t)(m0 + t)*NBK + nb] = s;
        }
    } else {
        float l[2][2];
        #pragma unroll
        for (int mi = 0; mi < 2; mi++){
            l[mi][0] = g_lse[m0 + wm*32 + mi*16 + g];
            l[mi][1] = g_lse[m0 + wm*32 + mi*16 + 8 + g];
        }
        #pragma unroll
        for (int mi = 0; mi < 2; mi++)
            #pragma unroll
            for (int ni = 0; ni < 8; ni++){
                int col0 = v0 + wn*64 + ni*8 + 2*tid4;
                int r0 = m0 + wm*32 + mi*16 + g;
                int r1 = r0 + 8;
                if (col0 < V_){
                    out[(size_t)r0*V_ + col0] = acc[mi][ni][0] - l[mi][0];
                    out[(size_t)r1*V_ + col0] = acc[mi][ni][2] - l[mi][1];
                }
                if (col0+1 < V_){
                    out[(size_t)r0*V_ + col0+1] = acc[mi][ni][1] - l[mi][0];
                    out[(size_t)r1*V_ + col0+1] = acc[mi][ni][3] - l[mi][1];
                }
            }
    }
}

// ---------------- kernel 4: combine partials -> lse per row ----------------
__global__ void k_reduce(){
    int r = blockIdx.x, t = threadIdx.x;   // 128 threads
    float m = -1e30f, s = 0.f;
    for (int p = t; p < NBK; p += 128)
        lse_merge(m, s, g_pmax[(size_t)r*NBK + p], g_psum[(size_t)r*NBK + p]);
    #pragma unroll
    for (int off = 16; off >= 1; off >>= 1){
        float m2 = __shfl_xor_sync(0xffffffffu, m, off);
        float s2 = __shfl_xor_sync(0xffffffffu, s, off);
        lse_merge(m, s, m2, s2);
    }
    __shared__ float sm_[4], ss_[4];
    int w = t >> 5;
    if ((t & 31) == 0){ sm_[w] = m; ss_[w] = s; }
    __syncthreads();
    if (t == 0){
        for (int w2 = 1; w2 < 4; w2++) lse_merge(m, s, sm_[w2], ss_[w2]);
        g_lse[r] = m + logf(s);
    }
}

// ---------------- launch ----------------
extern "C" void kernel_launch(void* const* d_in, const int* in_sizes, int n_in,
                              void* d_out, int out_size){
    const float* xs     = (const float*)d_in[0];   // [B, V]
    const float* metric = (const float*)d_in[1];   // [E, E]
    const float* emb    = (const float*)d_in[2];   // [V, E]
    const float* neg    = (const float*)d_in[3];   // [V, E]
    float* out = (float*)d_out;

    cudaFuncSetAttribute((const void*)k_gemm<0>,
                         cudaFuncAttributeMaxDynamicSharedMemorySize, SMEM_BYTES);
    cudaFuncSetAttribute((const void*)k_gemm<1>,
                         cudaFuncAttributeMaxDynamicSharedMemorySize, SMEM_BYTES);

    k_findidx<<<1184, 256>>>((const float4*)xs);
    k_q<<<B_, E_>>>(emb, metric);
    dim3 grid(NBK, B_/128);
    k_gemm<0><<<grid, 256, SMEM_BYTES>>>(neg, out);
    k_reduce<<<B_, 128>>>();
    k_gemm<1><<<grid, 256, SMEM_BYTES>>>(neg, out);
}

// round 4
// speedup vs baseline: 1.1376x; 1.1376x over previous
#include <cuda_runtime.h>
#include <cstdint>
#include <cstdio>

#define B_   1024
#define V_   50257
#define E_   128
#define NBK  393          // ceil(V/128)

#define BS_STRIDE 36      // 32 + 4 pad -> conflict-free B frag loads
#define A_FLOATS   (128*128)        // swizzled, no pad
#define BBUF_FLOATS (128*BS_STRIDE)
#define SMEM_BYTES ((A_FLOATS + 2*BBUF_FLOATS)*4)

// ---------------- device scratch (no allocation allowed) ----------------
__device__ int   g_idx[B_];
__device__ float g_q[B_*E_];
__device__ float g_pmax[B_*NBK];
__device__ float g_psum[B_*NBK];
__device__ float g_lse[B_];

// ---------------- helpers ----------------
__device__ __forceinline__ void lse_merge(float& m, float& s, float m2, float s2){
    float M = fmaxf(m, m2);
    s = s*__expf(m - M) + s2*__expf(m2 - M);
    m = M;
}

__device__ __forceinline__ void mma_tf32(float c[4], unsigned a0, unsigned a1,
                                         unsigned a2, unsigned a3,
                                         unsigned b0, unsigned b1){
    asm volatile(
        "mma.sync.aligned.m16n8k8.row.col.f32.tf32.tf32.f32 "
        "{%0,%1,%2,%3}, {%4,%5,%6,%7}, {%8,%9}, {%0,%1,%2,%3};\n"
        : "+f"(c[0]), "+f"(c[1]), "+f"(c[2]), "+f"(c[3])
        : "r"(a0), "r"(a1), "r"(a2), "r"(a3), "r"(b0), "r"(b1));
}

// ---------------- kernel 1: one-hot index extraction ----------------
__global__ void k_findidx(const float4* __restrict__ xs){
    long n4 = (long)B_*V_/4;
    for (long i = (long)blockIdx.x*blockDim.x + threadIdx.x; i < n4;
         i += (long)gridDim.x*blockDim.x){
        float4 v = __ldcs(xs + i);
        if (v.x!=0.f || v.y!=0.f || v.z!=0.f || v.w!=0.f){
            long base = i*4;
            if (v.x!=0.f){ long f=base;   g_idx[f/V_] = (int)(f%V_); }
            if (v.y!=0.f){ long f=base+1; g_idx[f/V_] = (int)(f%V_); }
            if (v.z!=0.f){ long f=base+2; g_idx[f/V_] = (int)(f%V_); }
            if (v.w!=0.f){ long f=base+3; g_idx[f/V_] = (int)(f%V_); }
        }
    }
}

// ---------------- kernel 2: q[b] = EMBEDM[idx[b]] @ metric ----------------
__global__ void k_q(const float* __restrict__ emb, const float* __restrict__ metric){
    __shared__ float se[E_];
    int b = blockIdx.x, t = threadIdx.x;
    int id = g_idx[b];
    se[t] = emb[(size_t)id*E_ + t];
    __syncthreads();
    float acc = 0.f;
    #pragma unroll 16
    for (int k = 0; k < E_; k++) acc = fmaf(se[k], metric[k*E_ + t], acc);
    g_q[b*E_ + t] = acc;
}

// ---------------- cp.async B-chunk loader ----------------
__device__ __forceinline__ void load_b_chunk(float* Bsb, const float* __restrict__ neg,
                                             int v0, int kc, int t){
    #pragma unroll
    for (int j = 0; j < 4; j++){
        int f = t + 256*j;
        int n = f >> 3, k4 = f & 7;
        int vrow = v0 + n;
        int ok = (vrow < V_);
        const float* gp = neg + (size_t)(ok ? vrow : 0)*E_ + kc + k4*4;
        unsigned saddr = (unsigned)__cvta_generic_to_shared(Bsb + n*BS_STRIDE + k4*4);
        int sz = ok ? 16 : 0;
        asm volatile("cp.async.cg.shared.global [%0], [%1], 16, %2;\n"
                     :: "r"(saddr), "l"(gp), "r"(sz));
    }
}

// ---------------- kernel 3: fused GEMM + score write + lse partials ----------------
__global__ __launch_bounds__(256, 2) void k_gemm(const float* __restrict__ neg,
                                                 float* __restrict__ out){
    extern __shared__ float sm[];
    float* As  = sm;                               // [128][128], XOR-swizzled
    float* Bs0 = sm + A_FLOATS;
    float* Bs1 = sm + A_FLOATS + BBUF_FLOATS;

    const int t    = threadIdx.x;
    const int lane = t & 31, wid = t >> 5;
    const int wm   = wid & 3;          // 4 warps in M -> 32 rows each
    const int wn   = wid >> 2;         // 2 warps in N -> 64 cols each
    const int g    = lane >> 2, tid4 = lane & 3;
    const int nb = blockIdx.x, mb = blockIdx.y;
    const int v0 = nb*128, m0 = mb*128;

    // prefetch B chunk 0
    load_b_chunk(Bs0, neg, v0, 0, t);
    asm volatile("cp.async.commit_group;\n" ::: "memory");

    // ---- load full-K A tile (q), XOR-swizzled: c4' = c4 ^ (row&7) ----
    {
        const float4* q4 = (const float4*)(g_q + (size_t)m0*E_);
        #pragma unroll
        for (int j = 0; j < 16; j++){
            int f = t + 256*j;
            int row = f >> 5, c4 = f & 31;
            float4 v = q4[row*32 + c4];
            *(float4*)(As + row*128 + (c4 ^ (row&7))*4) = v;
        }
    }

    float acc[2][8][4];
    #pragma unroll
    for (int mi = 0; mi < 2; mi++)
        #pragma unroll
        for (int ni = 0; ni < 8; ni++)
            #pragma unroll
            for (int c = 0; c < 4; c++) acc[mi][ni][c] = 0.f;

    // ---- pipelined main loop over 4 K-chunks of 32 ----
    #pragma unroll
    for (int c = 0; c < 4; c++){
        asm volatile("cp.async.wait_group 0;\n" ::: "memory");
        __syncthreads();
        if (c < 3){
            load_b_chunk((c & 1) ? Bs0 : Bs1, neg, v0, (c+1)*32, t);
            asm volatile("cp.async.commit_group;\n" ::: "memory");
        }
        const float* Bc = (c & 1) ? Bs1 : Bs0;
        const int kc = c*32;

        #pragma unroll
        for (int k8 = 0; k8 < 4; k8++){
            const int kA = kc + k8*8;
            const int kB = k8*8;
            const int c4a = (kA >> 2) ^ g;        // swizzled float4 index, lo half
            const int c4b = ((kA >> 2) + 1) ^ g;  // hi half (k+4)
            unsigned b0r[8], b1r[8];
            #pragma unroll
            for (int ni = 0; ni < 8; ni++){
                int n = wn*64 + ni*8 + g;
                b0r[ni] = __float_as_uint(Bc[n*BS_STRIDE + kB + tid4]);
                b1r[ni] = __float_as_uint(Bc[n*BS_STRIDE + kB + tid4 + 4]);
            }
            #pragma unroll
            for (int mi = 0; mi < 2; mi++){
                int m = wm*32 + mi*16;
                const float* r0 = As + (m+g  )*128;
                const float* r1 = As + (m+8+g)*128;
                unsigned a0 = __float_as_uint(r0[c4a*4 + tid4]);
                unsigned a1 = __float_as_uint(r1[c4a*4 + tid4]);
                unsigned a2 = __float_as_uint(r0[c4b*4 + tid4]);
                unsigned a3 = __float_as_uint(r1[c4b*4 + tid4]);
                #pragma unroll
                for (int ni = 0; ni < 8; ni++)
                    mma_tf32(acc[mi][ni], a0, a1, a2, a3, b0r[ni], b1r[ni]);
            }
        }
    }

    // ---- epilogue: write scores + per-row (max, sumexp) partials ----
    float rm[2][2] = {{-1e30f,-1e30f},{-1e30f,-1e30f}};
    float rs[2][2] = {{0.f,0.f},{0.f,0.f}};
    #pragma unroll
    for (int mi = 0; mi < 2; mi++)
        #pragma unroll
        for (int ni = 0; ni < 8; ni++){
            int col0 = v0 + wn*64 + ni*8 + 2*tid4;
            int r0 = m0 + wm*32 + mi*16 + g;
            int r1 = r0 + 8;
            if (col0 < V_){
                out[(size_t)r0*V_ + col0] = acc[mi][ni][0];
                out[(size_t)r1*V_ + col0] = acc[mi][ni][2];
                rm[mi][0] = fmaxf(rm[mi][0], acc[mi][ni][0]);
                rm[mi][1] = fmaxf(rm[mi][1], acc[mi][ni][2]);
            }
            if (col0+1 < V_){
                out[(size_t)r0*V_ + col0+1] = acc[mi][ni][1];
                out[(size_t)r1*V_ + col0+1] = acc[mi][ni][3];
                rm[mi][0] = fmaxf(rm[mi][0], acc[mi][ni][1]);
                rm[mi][1] = fmaxf(rm[mi][1], acc[mi][ni][3]);
            }
        }
    #pragma unroll
    for (int mi = 0; mi < 2; mi++)
        #pragma unroll
        for (int ni = 0; ni < 8; ni++){
            int col0 = v0 + wn*64 + ni*8 + 2*tid4;
            if (col0   < V_){ rs[mi][0] += __expf(acc[mi][ni][0] - rm[mi][0]);
                              rs[mi][1] += __expf(acc[mi][ni][2] - rm[mi][1]); }
            if (col0+1 < V_){ rs[mi][0] += __expf(acc[mi][ni][1] - rm[mi][0]);
                              rs[mi][1] += __expf(acc[mi][ni][3] - rm[mi][1]); }
        }
    // reduce across the 4 lanes sharing each row
    #pragma unroll
    for (int mi = 0; mi < 2; mi++)
        #pragma unroll
        for (int h = 0; h < 2; h++)
            #pragma unroll
            for (int off = 1; off <= 2; off <<= 1){
                float m2 = __shfl_xor_sync(0xffffffffu, rm[mi][h], off);
                float s2 = __shfl_xor_sync(0xffffffffu, rs[mi][h], off);
                lse_merge(rm[mi][h], rs[mi][h], m2, s2);
            }
    // cross-warp (wn) merge via smem (reuse As region; sync first: laggers may read As)
    __syncthreads();
    float* red = sm;   // [128 rows][2 wn][2]
    if (tid4 == 0){
        #pragma unroll
        for (int mi = 0; mi < 2; mi++)
            #pragma unroll
            for (int h = 0; h < 2; h++){
                int rl = wm*32 + mi*16 + h*8 + g;
                red[rl*4 + wn*2 + 0] = rm[mi][h];
                red[rl*4 + wn*2 + 1] = rs[mi][h];
            }
    }
    __syncthreads();
    if (t < 128){
        float m = red[t*4 + 0], s = red[t*4 + 1];
        lse_merge(m, s, red[t*4 + 2], red[t*4 + 3]);
        g_pmax[(size_t)(m0 + t)*NBK + nb] = m;
        g_psum[(size_t)(m0 + t)*NBK + nb] = s;
    }
}

// ---------------- kernel 4: combine partials -> lse per row ----------------
__global__ void k_reduce(){
    int r = blockIdx.x, t = threadIdx.x;   // 128 threads
    float m = -1e30f, s = 0.f;
    for (int p = t; p < NBK; p += 128)
        lse_merge(m, s, g_pmax[(size_t)r*NBK + p], g_psum[(size_t)r*NBK + p]);
    #pragma unroll
    for (int off = 16; off >= 1; off >>= 1){
        float m2 = __shfl_xor_sync(0xffffffffu, m, off);
        float s2 = __shfl_xor_sync(0xffffffffu, s, off);
        lse_merge(m, s, m2, s2);
    }
    __shared__ float sm_[4], ss_[4];
    int w = t >> 5;
    if ((t & 31) == 0){ sm_[w] = m; ss_[w] = s; }
    __syncthreads();
    if (t == 0){
        for (int w2 = 1; w2 < 4; w2++) lse_merge(m, s, sm_[w2], ss_[w2]);
        g_lse[r] = m + logf(s);
    }
}

// ---------------- kernel 5: out[r][v] -= lse[r], flattened float4 ----------------
__global__ void k_sub(float4* __restrict__ out4){
    long i4 = (long)blockIdx.x*blockDim.x + threadIdx.x;   // one float4 per thread
    long e = i4*4;
    if (e >= (long)B_*V_) return;
    int r = (int)(e / V_);
    int c = (int)(e - (long)r*V_);
    float4 v = out4[i4];
    if (c + 3 < V_){
        float l = g_lse[r];
        v.x -= l; v.y -= l; v.z -= l; v.w -= l;
    } else {
        // float4 straddles a row boundary (V_ odd)
        v.x -= g_lse[(c    >= V_) ? r+1 : r];
        v.y -= g_lse[(c+1  >= V_) ? r+1 : r];
        v.z -= g_lse[(c+2  >= V_) ? r+1 : r];
        v.w -= g_lse[(c+3  >= V_) ? r+1 : r];
    }
    out4[i4] = v;
}

// ---------------- launch ----------------
extern "C" void kernel_launch(void* const* d_in, const int* in_sizes, int n_in,
                              void* d_out, int out_size){
    const float* xs     = (const float*)d_in[0];   // [B, V]
    const float* metric = (const float*)d_in[1];   // [E, E]
    const float* emb    = (const float*)d_in[2];   // [V, E]
    const float* neg    = (const float*)d_in[3];   // [V, E]
    float* out = (float*)d_out;

    cudaFuncSetAttribute((const void*)k_gemm,
                         cudaFuncAttributeMaxDynamicSharedMemorySize, SMEM_BYTES);

    k_findidx<<<1184, 256>>>((const float4*)xs);
    k_q<<<B_, E_>>>(emb, metric);
    dim3 grid(NBK, B_/128);
    k_gemm<<<grid, 256, SMEM_BYTES>>>(neg, out);
    k_reduce<<<B_, 128>>>();
    long n4 = ((long)B_*V_) / 4;                  // 12,865,792 (exactly divisible)
    k_sub<<<(int)((n4 + 255)/256), 256>>>((float4*)out);
}

// round 9
// speedup vs baseline: 1.1811x; 1.0382x over previous
#include <cuda_runtime.h>
#include <cuda_fp16.h>
#include <cstdint>
#include <cstdio>

#define B_    1024
#define V_    50257
#define E_    128
#define NBK   393                 // ceil(V/128)
#define VPAD  (NBK*128)           // 50304

// ---------------- device scratch ----------------
__device__ int    g_idx[B_];
__device__ __half g_qh[B_*E_];
__device__ __half g_negh[(size_t)VPAD*E_];
__device__ float  g_pmax[B_*NBK];
__device__ float  g_psum[B_*NBK];
__device__ float  g_lse[B_];

// ---------------- helpers ----------------
__device__ __forceinline__ uint32_t smem_u32(const void* p){
    uint32_t a;
    asm("{ .reg .u64 t; cvta.to.shared.u64 t, %1; cvt.u32.u64 %0, t; }" : "=r"(a) : "l"(p));
    return a;
}
__device__ __forceinline__ uint32_t sw128(uint32_t off){ return off ^ ((off >> 3) & 0x70); }

__device__ __forceinline__ void lse_merge(float& m, float& s, float m2, float s2){
    float M = fmaxf(m, m2);
    s = s*__expf(m - M) + s2*__expf(m2 - M);
    m = M;
}

__device__ __forceinline__ void mma_f16(float c[4], const uint32_t a[4],
                                        uint32_t b0, uint32_t b1){
    asm volatile(
        "mma.sync.aligned.m16n8k16.row.col.f32.f16.f16.f32 "
        "{%0,%1,%2,%3}, {%4,%5,%6,%7}, {%8,%9}, {%0,%1,%2,%3};\n"
        : "+f"(c[0]), "+f"(c[1]), "+f"(c[2]), "+f"(c[3])
        : "r"(a[0]), "r"(a[1]), "r"(a[2]), "r"(a[3]), "r"(b0), "r"(b1));
}

__device__ __forceinline__ void ldsm_x4(uint32_t& r0, uint32_t& r1,
                                        uint32_t& r2, uint32_t& r3, uint32_t addr){
    asm volatile("ldmatrix.sync.aligned.m8n8.x4.shared.b16 {%0,%1,%2,%3}, [%4];"
                 : "=r"(r0), "=r"(r1), "=r"(r2), "=r"(r3) : "r"(addr));
}

// ---------------- kernel 1: one-hot index extraction ----------------
__global__ void k_findidx(const float4* __restrict__ xs){
    long n4 = (long)B_*V_/4;
    for (long i = (long)blockIdx.x*blockDim.x + threadIdx.x; i < n4;
         i += (long)gridDim.x*blockDim.x){
        float4 v = __ldcs(xs + i);
        if (v.x!=0.f || v.y!=0.f || v.z!=0.f || v.w!=0.f){
            long base = i*4;
            if (v.x!=0.f){ long f=base;   g_idx[f/V_] = (int)(f%V_); }
            if (v.y!=0.f){ long f=base+1; g_idx[f/V_] = (int)(f%V_); }
            if (v.z!=0.f){ long f=base+2; g_idx[f/V_] = (int)(f%V_); }
            if (v.w!=0.f){ long f=base+3; g_idx[f/V_] = (int)(f%V_); }
        }
    }
}

// ---------------- kernel 2: NEG -> fp16, zero-padded to VPAD rows ----------------
__global__ void k_prep(const float* __restrict__ neg){
    long i4 = (long)blockIdx.x*blockDim.x + threadIdx.x;   // one float4 = 4 elems
    if (i4 >= (long)VPAD*32) return;
    long e = i4*4;
    int row = (int)(e >> 7);
    float4 v = make_float4(0.f,0.f,0.f,0.f);
    if (row < V_) v = *(const float4*)(neg + e);
    __half2 a = __floats2half2_rn(v.x, v.y);
    __half2 b = __floats2half2_rn(v.z, v.w);
    uint2 p;
    p.x = *(uint32_t*)&a;
    p.y = *(uint32_t*)&b;
    *(uint2*)((char*)g_negh + e*2) = p;
}

// ---------------- kernel 3: q[b] = EMBEDM[idx[b]] @ metric -> fp16 ----------------
__global__ void k_q(const float* __restrict__ emb, const float* __restrict__ metric){
    __shared__ float se[E_];
    int b = blockIdx.x, t = threadIdx.x;
    int id = g_idx[b];
    se[t] = emb[(size_t)id*E_ + t];
    __syncthreads();
    float acc = 0.f;
    #pragma unroll 16
    for (int k = 0; k < E_; k++) acc = fmaf(se[k], metric[k*E_ + t], acc);
    g_qh[b*E_ + t] = __float2half_rn(acc);
}

// ---------------- GEMM pass (fp16 mma.sync m16n8k16) ----------------
// smem: As 2 chunks of [128 rows][64 fp16] SW128 at 0, Bs same at 32768. 64KB.
// EPI=0: per-row (max, sumexp) partials. EPI=1: out = score - lse.
#define SMEM_REQ 66560

template<int EPI>
__global__ __launch_bounds__(256) void k_pass(float* __restrict__ out){
    extern __shared__ char smc[];
    const uint32_t sb = smem_u32(smc);
    const int t    = threadIdx.x;
    const int lane = t & 31, wid = t >> 5;
    const int wm   = wid & 3;            // 4 warps in M (32 rows each)
    const int wn   = wid >> 2;           // 2 warps in N (64 cols each)
    const int g    = lane >> 2, t4 = lane & 3;
    const int mb = blockIdx.x, nb = blockIdx.y;
    const int m0 = mb*128, v0 = nb*128;

    // ---- cp.async loads: A (q fp16) and B (neg fp16), 16B granules, no guards ----
    #pragma unroll
    for (int j = 0; j < 8; j++){
        int id = t + j*256;                   // 0..2047
        int chunk = id >> 10, rem = id & 1023;
        int row = rem >> 3, c16 = rem & 7;
        const __half* gp = g_qh + (size_t)(m0 + row)*E_ + chunk*64 + c16*8;
        uint32_t sa = sb + chunk*16384 + sw128(row*128 + c16*16);
        asm volatile("cp.async.cg.shared.global [%0], [%1], 16;" :: "r"(sa), "l"(gp));
    }
    #pragma unroll
    for (int j = 0; j < 8; j++){
        int id = t + j*256;
        int chunk = id >> 10, rem = id & 1023;
        int row = rem >> 3, c16 = rem & 7;
        const __half* gp = g_negh + (size_t)(v0 + row)*E_ + chunk*64 + c16*8;
        uint32_t sa = sb + 32768 + chunk*16384 + sw128(row*128 + c16*16);
        asm volatile("cp.async.cg.shared.global [%0], [%1], 16;" :: "r"(sa), "l"(gp));
    }
    asm volatile("cp.async.commit_group;\n cp.async.wait_group 0;" ::: "memory");
    __syncthreads();

    float acc[2][8][4];
    #pragma unroll
    for (int mi = 0; mi < 2; mi++)
        #pragma unroll
        for (int ni = 0; ni < 8; ni++)
            #pragma unroll
            for (int c = 0; c < 4; c++) acc[mi][ni][c] = 0.f;

    // ---- 8 k16-steps ----
    #pragma unroll
    for (int ks = 0; ks < 8; ks++){
        const int chunk = ks >> 2, k8 = ks & 3;
        const uint32_t abase = sb + chunk*16384;
        const uint32_t bbase = sb + 32768 + chunk*16384;

        uint32_t a[2][4];
        #pragma unroll
        for (int mi = 0; mi < 2; mi++){
            int row = wm*32 + mi*16 + (lane & 7) + ((lane >> 3) & 1)*8;
            int gran = k8*2 + (lane >> 4);
            ldsm_x4(a[mi][0], a[mi][1], a[mi][2], a[mi][3],
                    abase + sw128(row*128 + gran*16));
        }
        uint32_t bb[8][2];
        #pragma unroll
        for (int p = 0; p < 4; p++){
            int mtx = lane >> 3;
            int n = wn*64 + p*16 + ((mtx >> 1) << 3) + (lane & 7);
            int gran = k8*2 + (mtx & 1);
            ldsm_x4(bb[2*p][0], bb[2*p][1], bb[2*p+1][0], bb[2*p+1][1],
                    bbase + sw128(n*128 + gran*16));
        }
        #pragma unroll
        for (int mi = 0; mi < 2; mi++)
            #pragma unroll
            for (int ni = 0; ni < 8; ni++)
                mma_f16(acc[mi][ni], a[mi], bb[ni][0], bb[ni][1]);
    }

    // ---- epilogue ----
    if (EPI == 0){
        float rm[2][2] = {{-1e30f,-1e30f},{-1e30f,-1e30f}};
        float rs[2][2] = {{0.f,0.f},{0.f,0.f}};
        #pragma unroll
        for (int mi = 0; mi < 2; mi++)
            #pragma unroll
            for (int ni = 0; ni < 8; ni++){
                int col0 = v0 + wn*64 + ni*8 + 2*t4;
                if (col0   < V_){ rm[mi][0] = fmaxf(rm[mi][0], acc[mi][ni][0]);
                                  rm[mi][1] = fmaxf(rm[mi][1], acc[mi][ni][2]); }
                if (col0+1 < V_){ rm[mi][0] = fmaxf(rm[mi][0], acc[mi][ni][1]);
                                  rm[mi][1] = fmaxf(rm[mi][1], acc[mi][ni][3]); }
            }
        #pragma unroll
        for (int mi = 0; mi < 2; mi++)
            #pragma unroll
            for (int ni = 0; ni < 8; ni++){
                int col0 = v0 + wn*64 + ni*8 + 2*t4;
                if (col0   < V_){ rs[mi][0] += __expf(acc[mi][ni][0] - rm[mi][0]);
                                  rs[mi][1] += __expf(acc[mi][ni][2] - rm[mi][1]); }
                if (col0+1 < V_){ rs[mi][0] += __expf(acc[mi][ni][1] - rm[mi][0]);
                                  rs[mi][1] += __expf(acc[mi][ni][3] - rm[mi][1]); }
            }
        #pragma unroll
        for (int mi = 0; mi < 2; mi++)
            #pragma unroll
            for (int h = 0; h < 2; h++)
                #pragma unroll
                for (int off = 1; off <= 2; off <<= 1){
                    float m2 = __shfl_xor_sync(0xffffffffu, rm[mi][h], off);
                    float s2 = __shfl_xor_sync(0xffffffffu, rs[mi][h], off);
                    lse_merge(rm[mi][h], rs[mi][h], m2, s2);
                }
        __syncthreads();
        float* red = (float*)smc;   // [128 rows][2 wn][2]
        if (t4 == 0){
            #pragma unroll
            for (int mi = 0; mi < 2; mi++)
                #pragma unroll
                for (int h = 0; h < 2; h++){
                    int rl = wm*32 + mi*16 + h*8 + g;
                    red[rl*4 + wn*2 + 0] = rm[mi][h];
                    red[rl*4 + wn*2 + 1] = rs[mi][h];
                }
        }
        __syncthreads();
        if (t < 128){
            float m = red[t*4 + 0], s = red[t*4 + 1];
            lse_merge(m, s, red[t*4 + 2], red[t*4 + 3]);
            g_pmax[(size_t)(m0 + t)*NBK + nb] = m;
            g_psum[(size_t)(m0 + t)*NBK + nb] = s;
        }
    } else {
        float l[2][2];
        #pragma unroll
        for (int mi = 0; mi < 2; mi++){
            l[mi][0] = g_lse[m0 + wm*32 + mi*16 + g];
            l[mi][1] = g_lse[m0 + wm*32 + mi*16 + 8 + g];
        }
        #pragma unroll
        for (int mi = 0; mi < 2; mi++)
            #pragma unroll
            for (int ni = 0; ni < 8; ni++){
                int col0 = v0 + wn*64 + ni*8 + 2*t4;
                int r0 = m0 + wm*32 + mi*16 + g;
                int r1 = r0 + 8;
                // scalar stores: V_ odd => float2 would be 4B-misaligned on odd rows
                if (col0 < V_){
                    out[(size_t)r0*V_ + col0] = acc[mi][ni][0] - l[mi][0];
                    out[(size_t)r1*V_ + col0] = acc[mi][ni][2] - l[mi][1];
                }
                if (col0 + 1 < V_){
                    out[(size_t)r0*V_ + col0+1] = acc[mi][ni][1] - l[mi][0];
                    out[(size_t)r1*V_ + col0+1] = acc[mi][ni][3] - l[mi][1];
                }
            }
    }
}

// ---------------- kernel: combine partials -> lse per row ----------------
__global__ void k_reduce(){
    int r = blockIdx.x, t = threadIdx.x;   // 128 threads
    float m = -1e30f, s = 0.f;
    for (int p = t; p < NBK; p += 128)
        lse_merge(m, s, g_pmax[(size_t)r*NBK + p], g_psum[(size_t)r*NBK + p]);
    #pragma unroll
    for (int off = 16; off >= 1; off >>= 1){
        float m2 = __shfl_xor_sync(0xffffffffu, m, off);
        float s2 = __shfl_xor_sync(0xffffffffu, s, off);
        lse_merge(m, s, m2, s2);
    }
    __shared__ float sm_[4], ss_[4];
    int w = t >> 5;
    if ((t & 31) == 0){ sm_[w] = m; ss_[w] = s; }
    __syncthreads();
    if (t == 0){
        for (int w2 = 1; w2 < 4; w2++) lse_merge(m, s, sm_[w2], ss_[w2]);
        g_lse[r] = m + logf(s);
    }
}

// ---------------- launch ----------------
extern "C" void kernel_launch(void* const* d_in, const int* in_sizes, int n_in,
                              void* d_out, int out_size){
    const float* xs     = (const float*)d_in[0];   // [B, V]
    const float* metric = (const float*)d_in[1];   // [E, E]
    const float* emb    = (const float*)d_in[2];   // [V, E]
    const float* neg    = (const float*)d_in[3];   // [V, E]
    float* out = (float*)d_out;

    cudaFuncSetAttribute((const void*)k_pass<0>,
                         cudaFuncAttributeMaxDynamicSharedMemorySize, SMEM_REQ);
    cudaFuncSetAttribute((const void*)k_pass<1>,
                         cudaFuncAttributeMaxDynamicSharedMemorySize, SMEM_REQ);

    k_findidx<<<1184, 256>>>((const float4*)xs);
    k_prep<<<(VPAD*32 + 255)/256, 256>>>(neg);
    k_q<<<B_, E_>>>(emb, metric);
    dim3 grid(B_/128, NBK);     // mb fastest -> 8 CTAs share each B tile in L2
    k_pass<0><<<grid, 256, SMEM_REQ>>>(out);
    k_reduce<<<B_, 128>>>();
    k_pass<1><<<grid, 256, SMEM_REQ>>>(out);
}

// round 11
// speedup vs baseline: 1.7974x; 1.5218x over previous
#include <cuda_runtime.h>
#include <cuda_fp16.h>
#include <cstdint>
#include <cstdio>

#define B_    1024
#define V_    50257
#define E_    128
#define NBK   393                 // ceil(V/128)
#define VPAD  (NBK*128)           // 50304

// ---------------- device scratch ----------------
__device__ int    g_idx[B_];
__device__ __half g_qh[B_*E_];
__device__ __half g_negh[(size_t)VPAD*E_];
__device__ float  g_pmax[B_*NBK];
__device__ float  g_psum[B_*NBK];
__device__ float  g_lse[B_];

// ---------------- helpers ----------------
__device__ __forceinline__ uint32_t smem_u32(const void* p){
    uint32_t a;
    asm("{ .reg .u64 t; cvta.to.shared.u64 t, %1; cvt.u32.u64 %0, t; }" : "=r"(a) : "l"(p));
    return a;
}
__device__ __forceinline__ uint32_t sw128(uint32_t off){ return off ^ ((off >> 3) & 0x70); }

__device__ __forceinline__ void lse_merge(float& m, float& s, float m2, float s2){
    float M = fmaxf(m, m2);
    s = s*__expf(m - M) + s2*__expf(m2 - M);
    m = M;
}

__device__ __forceinline__ void mma_f16(float c[4], const uint32_t a[4],
                                        uint32_t b0, uint32_t b1){
    asm volatile(
        "mma.sync.aligned.m16n8k16.row.col.f32.f16.f16.f32 "
        "{%0,%1,%2,%3}, {%4,%5,%6,%7}, {%8,%9}, {%0,%1,%2,%3};\n"
        : "+f"(c[0]), "+f"(c[1]), "+f"(c[2]), "+f"(c[3])
        : "r"(a[0]), "r"(a[1]), "r"(a[2]), "r"(a[3]), "r"(b0), "r"(b1));
}

__device__ __forceinline__ void ldsm_x4(uint32_t& r0, uint32_t& r1,
                                        uint32_t& r2, uint32_t& r3, uint32_t addr){
    asm volatile("ldmatrix.sync.aligned.m8n8.x4.shared.b16 {%0,%1,%2,%3}, [%4];"
                 : "=r"(r0), "=r"(r1), "=r"(r2), "=r"(r3) : "r"(addr));
}

// ---------------- kernel 1: one-hot index extraction ----------------
__global__ void k_findidx(const float4* __restrict__ xs){
    long n4 = (long)B_*V_/4;
    for (long i = (long)blockIdx.x*blockDim.x + threadIdx.x; i < n4;
         i += (long)gridDim.x*blockDim.x){
        float4 v = __ldcs(xs + i);
        if (v.x!=0.f || v.y!=0.f || v.z!=0.f || v.w!=0.f){
            long base = i*4;
            if (v.x!=0.f){ long f=base;   g_idx[f/V_] = (int)(f%V_); }
            if (v.y!=0.f){ long f=base+1; g_idx[f/V_] = (int)(f%V_); }
            if (v.z!=0.f){ long f=base+2; g_idx[f/V_] = (int)(f%V_); }
            if (v.w!=0.f){ long f=base+3; g_idx[f/V_] = (int)(f%V_); }
        }
    }
}

// ---------------- kernel 2: NEG -> fp16, zero-padded to VPAD rows ----------------
__global__ void k_prep(const float* __restrict__ neg){
    long i4 = (long)blockIdx.x*blockDim.x + threadIdx.x;   // one float4 = 4 elems
    if (i4 >= (long)VPAD*32) return;
    long e = i4*4;
    int row = (int)(e >> 7);
    float4 v = make_float4(0.f,0.f,0.f,0.f);
    if (row < V_) v = *(const float4*)(neg + e);
    __half2 a = __floats2half2_rn(v.x, v.y);
    __half2 b = __floats2half2_rn(v.z, v.w);
    uint2 p;
    p.x = *(uint32_t*)&a;
    p.y = *(uint32_t*)&b;
    *(uint2*)((char*)g_negh + e*2) = p;
}

// ---------------- kernel 3: q[b] = EMBEDM[idx[b]] @ metric -> fp16 ----------------
__global__ void k_q(const float* __restrict__ emb, const float* __restrict__ metric){
    __shared__ float se[E_];
    int b = blockIdx.x, t = threadIdx.x;
    int id = g_idx[b];
    se[t] = emb[(size_t)id*E_ + t];
    __syncthreads();
    float acc = 0.f;
    #pragma unroll 16
    for (int k = 0; k < E_; k++) acc = fmaf(se[k], metric[k*E_ + t], acc);
    g_qh[b*E_ + t] = __float2half_rn(acc);
}

// ---------------- GEMM pass (fp16 mma.sync m16n8k16) ----------------
// smem mainloop: As 2 chunks [128][64] fp16 SW128 at 0, Bs same at 32768 (64KB).
// EPI=1 reuses smem as fp32 stage [128][132] = 67.6KB.
#define STG_STRIDE 132
#define SMEM_REQ   (128*STG_STRIDE*4)    // 67584

template<int EPI>
__global__ __launch_bounds__(256) void k_pass(float* __restrict__ out){
    extern __shared__ char smc[];
    const uint32_t sb = smem_u32(smc);
    const int t    = threadIdx.x;
    const int lane = t & 31, wid = t >> 5;
    const int wm   = wid & 3;            // 4 warps in M (32 rows each)
    const int wn   = wid >> 2;           // 2 warps in N (64 cols each)
    const int g    = lane >> 2, t4 = lane & 3;
    const int mb = blockIdx.x, nb = blockIdx.y;
    const int m0 = mb*128, v0 = nb*128;

    // ---- cp.async loads: A (q fp16) and B (neg fp16), 16B granules, no guards ----
    #pragma unroll
    for (int j = 0; j < 8; j++){
        int id = t + j*256;                   // 0..2047
        int chunk = id >> 10, rem = id & 1023;
        int row = rem >> 3, c16 = rem & 7;
        const __half* gp = g_qh + (size_t)(m0 + row)*E_ + chunk*64 + c16*8;
        uint32_t sa = sb + chunk*16384 + sw128(row*128 + c16*16);
        asm volatile("cp.async.cg.shared.global [%0], [%1], 16;" :: "r"(sa), "l"(gp));
    }
    #pragma unroll
    for (int j = 0; j < 8; j++){
        int id = t + j*256;
        int chunk = id >> 10, rem = id & 1023;
        int row = rem >> 3, c16 = rem & 7;
        const __half* gp = g_negh + (size_t)(v0 + row)*E_ + chunk*64 + c16*8;
        uint32_t sa = sb + 32768 + chunk*16384 + sw128(row*128 + c16*16);
        asm volatile("cp.async.cg.shared.global [%0], [%1], 16;" :: "r"(sa), "l"(gp));
    }
    asm volatile("cp.async.commit_group;\n cp.async.wait_group 0;" ::: "memory");
    __syncthreads();

    float acc[2][8][4];
    #pragma unroll
    for (int mi = 0; mi < 2; mi++)
        #pragma unroll
        for (int ni = 0; ni < 8; ni++)
            #pragma unroll
            for (int c = 0; c < 4; c++) acc[mi][ni][c] = 0.f;

    // ---- 8 k16-steps ----
    #pragma unroll
    for (int ks = 0; ks < 8; ks++){
        const int chunk = ks >> 2, k8 = ks & 3;
        const uint32_t abase = sb + chunk*16384;
        const uint32_t bbase = sb + 32768 + chunk*16384;

        uint32_t a[2][4];
        #pragma unroll
        for (int mi = 0; mi < 2; mi++){
            int row = wm*32 + mi*16 + (lane & 7) + ((lane >> 3) & 1)*8;
            int gran = k8*2 + (lane >> 4);
            ldsm_x4(a[mi][0], a[mi][1], a[mi][2], a[mi][3],
                    abase + sw128(row*128 + gran*16));
        }
        uint32_t bb[8][2];
        #pragma unroll
        for (int p = 0; p < 4; p++){
            int mtx = lane >> 3;
            int n = wn*64 + p*16 + ((mtx >> 1) << 3) + (lane & 7);
            int gran = k8*2 + (mtx & 1);
            ldsm_x4(bb[2*p][0], bb[2*p][1], bb[2*p+1][0], bb[2*p+1][1],
                    bbase + sw128(n*128 + gran*16));
        }
        #pragma unroll
        for (int mi = 0; mi < 2; mi++)
            #pragma unroll
            for (int ni = 0; ni < 8; ni++)
                mma_f16(acc[mi][ni], a[mi], bb[ni][0], bb[ni][1]);
    }

    // ---- epilogue ----
    if (EPI == 0){
        float rm[2][2] = {{-1e30f,-1e30f},{-1e30f,-1e30f}};
        float rs[2][2] = {{0.f,0.f},{0.f,0.f}};
        #pragma unroll
        for (int mi = 0; mi < 2; mi++)
            #pragma unroll
            for (int ni = 0; ni < 8; ni++){
                int col0 = v0 + wn*64 + ni*8 + 2*t4;
                if (col0   < V_){ rm[mi][0] = fmaxf(rm[mi][0], acc[mi][ni][0]);
                                  rm[mi][1] = fmaxf(rm[mi][1], acc[mi][ni][2]); }
                if (col0+1 < V_){ rm[mi][0] = fmaxf(rm[mi][0], acc[mi][ni][1]);
                                  rm[mi][1] = fmaxf(rm[mi][1], acc[mi][ni][3]); }
            }
        #pragma unroll
        for (int mi = 0; mi < 2; mi++)
            #pragma unroll
            for (int ni = 0; ni < 8; ni++){
                int col0 = v0 + wn*64 + ni*8 + 2*t4;
                if (col0   < V_){ rs[mi][0] += __expf(acc[mi][ni][0] - rm[mi][0]);
                                  rs[mi][1] += __expf(acc[mi][ni][2] - rm[mi][1]); }
                if (col0+1 < V_){ rs[mi][0] += __expf(acc[mi][ni][1] - rm[mi][0]);
                                  rs[mi][1] += __expf(acc[mi][ni][3] - rm[mi][1]); }
            }
        #pragma unroll
        for (int mi = 0; mi < 2; mi++)
            #pragma unroll
            for (int h = 0; h < 2; h++)
                #pragma unroll
                for (int off = 1; off <= 2; off <<= 1){
                    float m2 = __shfl_xor_sync(0xffffffffu, rm[mi][h], off);
                    float s2 = __shfl_xor_sync(0xffffffffu, rs[mi][h], off);
                    lse_merge(rm[mi][h], rs[mi][h], m2, s2);
                }
        __syncthreads();
        float* red = (float*)smc;   // [128 rows][2 wn][2]
        if (t4 == 0){
            #pragma unroll
            for (int mi = 0; mi < 2; mi++)
                #pragma unroll
                for (int h = 0; h < 2; h++){
                    int rl = wm*32 + mi*16 + h*8 + g;
                    red[rl*4 + wn*2 + 0] = rm[mi][h];
                    red[rl*4 + wn*2 + 1] = rs[mi][h];
                }
        }
        __syncthreads();
        if (t < 128){
            float m = red[t*4 + 0], s = red[t*4 + 1];
            lse_merge(m, s, red[t*4 + 2], red[t*4 + 3]);
            g_pmax[(size_t)(m0 + t)*NBK + nb] = m;
            g_psum[(size_t)(m0 + t)*NBK + nb] = s;
        }
    } else {
        // ---- staged store: smem [128][STG_STRIDE] fp32, subtract lse at STS ----
        float l[2][2];
        #pragma unroll
        for (int mi = 0; mi < 2; mi++){
            l[mi][0] = g_lse[m0 + wm*32 + mi*16 + g];
            l[mi][1] = g_lse[m0 + wm*32 + mi*16 + 8 + g];
        }
        float* stage = (float*)smc;
        __syncthreads();               // mainloop smem reads complete before overwrite
        #pragma unroll
        for (int mi = 0; mi < 2; mi++){
            int rowL0 = wm*32 + mi*16 + g;
            int rowL1 = rowL0 + 8;
            #pragma unroll
            for (int ni = 0; ni < 8; ni++){
                int colL = wn*64 + ni*8 + 2*t4;
                *(float2*)(stage + rowL0*STG_STRIDE + colL) =
                    make_float2(acc[mi][ni][0]-l[mi][0], acc[mi][ni][1]-l[mi][0]);
                *(float2*)(stage + rowL1*STG_STRIDE + colL) =
                    make_float2(acc[mi][ni][2]-l[mi][1], acc[mi][ni][3]-l[mi][1]);
            }
        }
        __syncthreads();
        // coalesced writes: warp wid owns rows wid*16..wid*16+15, 4x128B per row
        const int ncols = min(128, V_ - v0);
        float* obase = out + (size_t)(m0 + wid*16)*V_ + v0;
        #pragma unroll
        for (int i = 0; i < 16; i++){
            const float* srow = stage + (wid*16 + i)*STG_STRIDE;
            #pragma unroll
            for (int j = 0; j < 4; j++){
                int col = j*32 + lane;
                if (col < ncols) obase[col] = srow[col];
            }
            obase += V_;
        }
    }
}

// ---------------- kernel: combine partials -> lse per row ----------------
__global__ void k_reduce(){
    int r = blockIdx.x, t = threadIdx.x;   // 128 threads
    float m = -1e30f, s = 0.f;
    for (int p = t; p < NBK; p += 128)
        lse_merge(m, s, g_pmax[(size_t)r*NBK + p], g_psum[(size_t)r*NBK + p]);
    #pragma unroll
    for (int off = 16; off >= 1; off >>= 1){
        float m2 = __shfl_xor_sync(0xffffffffu, m, off);
        float s2 = __shfl_xor_sync(0xffffffffu, s, off);
        lse_merge(m, s, m2, s2);
    }
    __shared__ float sm_[4], ss_[4];
    int w = t >> 5;
    if ((t & 31) == 0){ sm_[w] = m; ss_[w] = s; }
    __syncthreads();
    if (t == 0){
        for (int w2 = 1; w2 < 4; w2++) lse_merge(m, s, sm_[w2], ss_[w2]);
        g_lse[r] = m + logf(s);
    }
}

// ---------------- launch ----------------
extern "C" void kernel_launch(void* const* d_in, const int* in_sizes, int n_in,
                              void* d_out, int out_size){
    const float* xs     = (const float*)d_in[0];   // [B, V]
    const float* metric = (const float*)d_in[1];   // [E, E]
    const float* emb    = (const float*)d_in[2];   // [V, E]
    const float* neg    = (const float*)d_in[3];   // [V, E]
    float* out = (float*)d_out;

    cudaFuncSetAttribute((const void*)k_pass<0>,
                         cudaFuncAttributeMaxDynamicSharedMemorySize, SMEM_REQ);
    cudaFuncSetAttribute((const void*)k_pass<1>,
                         cudaFuncAttributeMaxDynamicSharedMemorySize, SMEM_REQ);

    k_findidx<<<1184, 256>>>((const float4*)xs);
    k_prep<<<(VPAD*32 + 255)/256, 256>>>(neg);
    k_q<<<B_, E_>>>(emb, metric);
    dim3 grid(B_/128, NBK);     // mb fastest -> 8 CTAs share each B tile in L2
    k_pass<0><<<grid, 256, SMEM_REQ>>>(out);
    k_reduce<<<B_, 128>>>();
    k_pass<1><<<grid, 256, SMEM_REQ>>>(out);
}